// round 3
// baseline (speedup 1.0000x reference)
#include <cuda_runtime.h>

// SMorph: out = sum_k (x_p+f_k) e^{a(x_p+f_k)} / sum_k e^{a(x_p+f_k)}
// Factored: G=exp(a*x), H=x*G, E_k=exp(a*f_k), F_k=f_k*E_k
//   numA = sum E_k*H, den = sum E_k*G, numB = sum F_k*G, out=(numA+numB)/den
// f32x2 packed math: acc{numA,den} += {E,E}*{h,g};  acc{junk,numB} += {0,F}*{h,g}
// Warp = 8 smem rows x 4 lanes, 8 contiguous outputs/thread -> conflict-free LDS.

namespace {
constexpr int BATCH = 8;
constexpr int HH = 192, WW = 192;
constexpr int CO = 8;
constexpr int KH = 7, KW = 7;
constexpr int HO = 186, WO = 186;

constexpr int TILE_X = 64;
constexpr int TILE_Y = 32;
constexpr int ITX = TILE_X + KW - 1; // 70
constexpr int ITY = TILE_Y + KH - 1; // 38
constexpr int PITCH = 71;            // 71 mod 32 = 7 -> row stagger
constexpr int OPT = 8;               // outputs per thread (contiguous x)
constexpr int WINW = OPT + KW - 1;   // 14
}

__device__ __forceinline__ void vfma(unsigned long long& acc,
                                     unsigned long long a,
                                     unsigned long long b) {
    asm("fma.rn.f32x2 %0, %1, %2, %0;" : "+l"(acc) : "l"(a), "l"(b));
}

__global__ __launch_bounds__(256, 3)
void smorph_kernel(const float* __restrict__ x,
                   const float* __restrict__ filt,
                   const float* __restrict__ alpha,
                   float* __restrict__ out)
{
    __shared__ float sG[ITY * PITCH];
    __shared__ float sH[ITY * PITCH];
    __shared__ unsigned long long sEE[KH * KW];  // {E, E}
    __shared__ unsigned long long sFF[KH * KW];  // {0, F}

    const int bc  = blockIdx.z;        // b*8 + c
    const int c   = bc & 7;
    const int tid = threadIdx.x;

    const float a = alpha[c];

    if (tid < KH * KW) {
        float f = filt[c * (KH * KW) + tid];
        float e = __expf(a * f);
        float fe = f * e;
        unsigned long long ee, ff;
        asm("mov.b64 %0, {%1, %2};" : "=l"(ee) : "f"(e), "f"(e));
        asm("mov.b64 %0, {%1, %2};" : "=l"(ff) : "f"(0.0f), "f"(fe));
        sEE[tid] = ee;
        sFF[tid] = ff;
    }

    const int gx0 = blockIdx.x * TILE_X;
    const int gy0 = blockIdx.y * TILE_Y;
    const float* xb = x + (bc >> 3) * (HH * WW);

    // Cooperative tile fill: G = exp(a*x), H = x*G
    for (int i = tid; i < ITY * ITX; i += 256) {
        int iy = i / ITX;
        int ix = i - iy * ITX;
        int gy = gy0 + iy;
        int gx = gx0 + ix;
        float v = (gy < HH && gx < WW) ? xb[gy * WW + gx] : 0.0f;
        float g = __expf(a * v);
        sG[iy * PITCH + ix] = g;
        sH[iy * PITCH + ix] = v * g;
    }
    __syncthreads();

    // Warp geometry: 8 rows x 4 lanes, 8 contiguous outputs per thread.
    const int lane = tid & 31;
    const int warp = tid >> 5;
    const int tx = lane & 3;          // 0..3
    const int sy = lane >> 2;         // 0..7
    const int wx = warp & 1;          // 0..1
    const int wy = warp >> 1;         // 0..3
    const int lx = (wx * 4 + tx) * OPT;   // 0..56
    const int ly = wy * 8 + sy;           // 0..31

    unsigned long long accA[OPT];  // {numA, den}
    unsigned long long accB[OPT];  // {junk, numB}
    #pragma unroll
    for (int o = 0; o < OPT; o++) { accA[o] = 0ull; accB[o] = 0ull; }

    #pragma unroll
    for (int ky = 0; ky < KH; ky++) {
        const float* gr = &sG[(ly + ky) * PITCH + lx];
        const float* hr = &sH[(ly + ky) * PITCH + lx];
        unsigned long long w[WINW];   // {h, g}
        #pragma unroll
        for (int j = 0; j < WINW; j++) {
            float g = gr[j];
            float h = hr[j];
            asm("mov.b64 %0, {%1, %2};" : "=l"(w[j]) : "f"(h), "f"(g));
        }
        #pragma unroll
        for (int kx = 0; kx < KW; kx++) {
            const unsigned long long ee = sEE[ky * KW + kx]; // broadcast
            const unsigned long long ff = sFF[ky * KW + kx]; // broadcast
            #pragma unroll
            for (int o = 0; o < OPT; o++) {
                vfma(accA[o], ee, w[kx + o]);
                vfma(accB[o], ff, w[kx + o]);
            }
        }
    }

    const int oy = gy0 + ly;
    const int ox0 = gx0 + lx;
    if (oy < HO) {
        float* orow = out + ((long)bc * HO + oy) * WO;
        #pragma unroll
        for (int o = 0; o < OPT; o++) {
            float numA, den, junk, numB;
            asm("mov.b64 {%0, %1}, %2;" : "=f"(numA), "=f"(den)  : "l"(accA[o]));
            asm("mov.b64 {%0, %1}, %2;" : "=f"(junk), "=f"(numB) : "l"(accB[o]));
            if (ox0 + o < WO)
                orow[ox0 + o] = __fdividef(numA + numB, den);
        }
    }
}

extern "C" void kernel_launch(void* const* d_in, const int* in_sizes, int n_in,
                              void* d_out, int out_size) {
    const float* x     = (const float*)d_in[0];   // (8,1,192,192)
    const float* filt  = (const float*)d_in[1];   // (8,1,7,7)
    const float* alpha = (const float*)d_in[2];   // (8,1)
    float* out = (float*)d_out;                   // (8,8,186,186)

    dim3 block(256);
    dim3 grid((WO + TILE_X - 1) / TILE_X,   // 3
              (HO + TILE_Y - 1) / TILE_Y,   // 6
              BATCH * CO);                  // 64
    smorph_kernel<<<grid, block>>>(x, filt, alpha, out);
}

// round 4
// speedup vs baseline: 1.8261x; 1.8261x over previous
#include <cuda_runtime.h>

// SMorph: out = sum_k (x_p+f_k) e^{a(x_p+f_k)} / sum_k e^{a(x_p+f_k)}
// Factored: G=exp(a*x), H=x*G, E_k=exp(a*f_k), F_k=f_k*E_k
//   num = sum_k E_k*H + F_k*G;  den = sum_k E_k*G
// => three 7x7 correlations over smem-resident G/H planes.
// Warp = 4 smem rows x 8 lanes (4 outputs/thread): provably conflict-free LDS
// against PITCH=71 (bank = 4tx + 7sy + j mod 32 has no intra-warp collision).

namespace {
constexpr int BATCH = 8;
constexpr int HH = 192, WW = 192;
constexpr int CO = 8;
constexpr int KH = 7, KW = 7;
constexpr int HO = 186, WO = 186;

constexpr int TILE_X = 64;           // output tile width
constexpr int TILE_Y = 16;           // output tile height
constexpr int ITX = TILE_X + KW - 1; // 70 input cols
constexpr int ITY = TILE_Y + KH - 1; // 22 input rows
constexpr int PITCH = 71;            // odd pitch -> per-row bank stagger of 7
}

__global__ __launch_bounds__(256, 4)
void smorph_kernel(const float* __restrict__ x,
                   const float* __restrict__ filt,
                   const float* __restrict__ alpha,
                   float* __restrict__ out)
{
    __shared__ float sG[ITY * PITCH];
    __shared__ float sH[ITY * PITCH];
    __shared__ float2 sEF[KH * KW];   // {E, F} per tap

    const int bc  = blockIdx.z;       // b*8 + c
    const int c   = bc & 7;
    const int tid = threadIdx.x;

    const float a = alpha[c];

    if (tid < KH * KW) {
        float f = filt[c * (KH * KW) + tid];
        float e = __expf(a * f);
        sEF[tid] = make_float2(e, f * e);
    }

    const int gx0 = blockIdx.x * TILE_X;
    const int gy0 = blockIdx.y * TILE_Y;
    const float* xb = x + (bc >> 3) * (HH * WW);

    // Cooperative tile fill: G = exp(a*x), H = x*G
    for (int i = tid; i < ITY * ITX; i += 256) {
        int iy = i / ITX;
        int ix = i - iy * ITX;
        int gy = gy0 + iy;
        int gx = gx0 + ix;
        float v = (gy < HH && gx < WW) ? xb[gy * WW + gx] : 0.0f;
        float g = __expf(a * v);
        sG[iy * PITCH + ix] = g;
        sH[iy * PITCH + ix] = v * g;
    }
    __syncthreads();

    // Conflict-free warp geometry: 4 rows x 8 lanes, 4 outputs/thread.
    const int lane = tid & 31;
    const int warp = tid >> 5;        // 0..7
    const int tx = lane & 7;          // 0..7
    const int sy = lane >> 3;         // 0..3
    const int wx = warp & 1;          // 0..1
    const int wy = warp >> 1;         // 0..3
    const int lx = (wx * 8 + tx) * 4; // 0..60
    const int ly = wy * 4 + sy;       // 0..15

    float num0 = 0.f, num1 = 0.f, num2 = 0.f, num3 = 0.f;
    float den0 = 0.f, den1 = 0.f, den2 = 0.f, den3 = 0.f;

    #pragma unroll
    for (int ky = 0; ky < KH; ky++) {
        const float* gr = &sG[(ly + ky) * PITCH + lx];
        const float* hr = &sH[(ly + ky) * PITCH + lx];
        float g[KW + 3], h[KW + 3];
        #pragma unroll
        for (int i = 0; i < KW + 3; i++) {
            g[i] = gr[i];
            h[i] = hr[i];
        }
        #pragma unroll
        for (int kx = 0; kx < KW; kx++) {
            const float2 ef = sEF[ky * KW + kx];  // uniform LDS.64 broadcast
            const float E = ef.x, F = ef.y;
            num0 = fmaf(E, h[kx + 0], fmaf(F, g[kx + 0], num0));
            den0 = fmaf(E, g[kx + 0], den0);
            num1 = fmaf(E, h[kx + 1], fmaf(F, g[kx + 1], num1));
            den1 = fmaf(E, g[kx + 1], den1);
            num2 = fmaf(E, h[kx + 2], fmaf(F, g[kx + 2], num2));
            den2 = fmaf(E, g[kx + 2], den2);
            num3 = fmaf(E, h[kx + 3], fmaf(F, g[kx + 3], num3));
            den3 = fmaf(E, g[kx + 3], den3);
        }
    }

    const int oy = gy0 + ly;
    const int ox = gx0 + lx;
    if (oy < HO) {
        float* orow = out + ((long)bc * HO + oy) * WO;
        if (ox + 0 < WO) orow[ox + 0] = __fdividef(num0, den0);
        if (ox + 1 < WO) orow[ox + 1] = __fdividef(num1, den1);
        if (ox + 2 < WO) orow[ox + 2] = __fdividef(num2, den2);
        if (ox + 3 < WO) orow[ox + 3] = __fdividef(num3, den3);
    }
}

extern "C" void kernel_launch(void* const* d_in, const int* in_sizes, int n_in,
                              void* d_out, int out_size) {
    const float* x     = (const float*)d_in[0];   // (8,1,192,192)
    const float* filt  = (const float*)d_in[1];   // (8,1,7,7)
    const float* alpha = (const float*)d_in[2];   // (8,1)
    float* out = (float*)d_out;                   // (8,8,186,186)

    dim3 block(256);
    dim3 grid((WO + TILE_X - 1) / TILE_X,   // 3
              (HO + TILE_Y - 1) / TILE_Y,   // 12
              BATCH * CO);                  // 64
    smorph_kernel<<<grid, block>>>(x, filt, alpha, out);
}

// round 5
// speedup vs baseline: 1.8708x; 1.0245x over previous
#include <cuda_runtime.h>

// SMorph: out = sum_k (x_p+f_k) e^{a(x_p+f_k)} / sum_k e^{a(x_p+f_k)}
// Factored: G=exp(a*x), H=x*G, E_k=exp(a*f_k), F_k=f_k*E_k
//   numA = sum E_k*H; den = sum E_k*G; numB = sum F_k*G; out=(numA+numB)/den
// Packed f32x2 with ZERO pack movs: smem holds interleaved {h,g} float2;
// taps held as float4 {E,E,0,F}. Per tap-output: 2x fma.rn.f32x2 (vs 3 FFMA).
//   {numA,den} += {E,E}*{h,g};   {0,numB} += {0,F}*{h,g}
// Warp = 4 cols x 8 rows, pitch P2=81 (== 1 mod 16): every 16-lane LDS.64
// phase covers 16 distinct pair-banks -> conflict-free.

namespace {
constexpr int BATCH = 8;
constexpr int HH = 192, WW = 192;
constexpr int CO = 8;
constexpr int KH = 7, KW = 7;
constexpr int HO = 186, WO = 186;

constexpr int TILE_X = 64;
constexpr int TILE_Y = 16;
constexpr int ITX = TILE_X + KW - 1; // 70
constexpr int ITY = TILE_Y + KH - 1; // 22
constexpr int P2  = 81;              // float2 pitch, 81 mod 16 == 1
constexpr int OPT = 4;
constexpr int WINW = OPT + KW - 1;   // 10
}

__device__ __forceinline__ void vfma(unsigned long long& acc,
                                     unsigned long long a,
                                     unsigned long long b) {
    asm("fma.rn.f32x2 %0, %1, %2, %0;" : "+l"(acc) : "l"(a), "l"(b));
}

__global__ __launch_bounds__(256, 4)
void smorph_kernel(const float* __restrict__ x,
                   const float* __restrict__ filt,
                   const float* __restrict__ alpha,
                   float* __restrict__ out)
{
    __shared__ float2 sGH[ITY * P2];     // {h, g} interleaved
    __shared__ float4 sTap[KH * KW];     // {E, E, 0, F}

    const int bc  = blockIdx.z;          // b*8 + c
    const int c   = bc & 7;
    const int tid = threadIdx.x;

    const float a = alpha[c];

    if (tid < KH * KW) {
        float f = filt[c * (KH * KW) + tid];
        float e = __expf(a * f);
        sTap[tid] = make_float4(e, e, 0.0f, f * e);
    }

    const int gx0 = blockIdx.x * TILE_X;
    const int gy0 = blockIdx.y * TILE_Y;
    const float* xb = x + (bc >> 3) * (HH * WW);

    // Cooperative tile fill: {h,g} = {x*exp(a*x), exp(a*x)}
    for (int i = tid; i < ITY * ITX; i += 256) {
        int iy = i / ITX;
        int ix = i - iy * ITX;
        int gy = gy0 + iy;
        int gx = gx0 + ix;
        float v = (gy < HH && gx < WW) ? xb[gy * WW + gx] : 0.0f;
        float g = __expf(a * v);
        sGH[iy * P2 + ix] = make_float2(v * g, g);
    }
    __syncthreads();

    // Warp = 4 cols x 8 rows; 4 contiguous outputs per thread.
    const int lane = tid & 31;
    const int warp = tid >> 5;          // 0..7
    const int txb = lane & 3;           // 0..3
    const int sy  = lane >> 2;          // 0..7
    const int wx  = warp & 3;           // 0..3
    const int wy  = warp >> 2;          // 0..1
    const int lx  = (wx * 4 + txb) * OPT;  // 0..60
    const int ly  = wy * 8 + sy;           // 0..15

    unsigned long long accA[OPT];  // {numA, den}
    unsigned long long accB[OPT];  // {0, numB}
    #pragma unroll
    for (int o = 0; o < OPT; o++) { accA[o] = 0ull; accB[o] = 0ull; }

    #pragma unroll
    for (int ky = 0; ky < KH; ky++) {
        const unsigned long long* row =
            reinterpret_cast<const unsigned long long*>(&sGH[(ly + ky) * P2 + lx]);
        unsigned long long w[WINW];
        #pragma unroll
        for (int j = 0; j < WINW; j++) w[j] = row[j];   // LDS.64, conflict-free

        const ulonglong2* tap =
            reinterpret_cast<const ulonglong2*>(&sTap[ky * KW]);
        #pragma unroll
        for (int kx = 0; kx < KW; kx++) {
            const ulonglong2 t = tap[kx];   // LDS.128 broadcast {E,E | 0,F}
            #pragma unroll
            for (int o = 0; o < OPT; o++) {
                vfma(accA[o], t.x, w[kx + o]);
                vfma(accB[o], t.y, w[kx + o]);
            }
        }
    }

    const int oy = gy0 + ly;
    const int ox = gx0 + lx;
    if (oy < HO) {
        float* orow = out + ((long)bc * HO + oy) * WO;
        #pragma unroll
        for (int o = 0; o < OPT; o++) {
            float numA, den, z, numB;
            asm("mov.b64 {%0, %1}, %2;" : "=f"(numA), "=f"(den)  : "l"(accA[o]));
            asm("mov.b64 {%0, %1}, %2;" : "=f"(z),    "=f"(numB) : "l"(accB[o]));
            if (ox + o < WO)
                orow[ox + o] = __fdividef(numA + numB, den);
        }
    }
}

extern "C" void kernel_launch(void* const* d_in, const int* in_sizes, int n_in,
                              void* d_out, int out_size) {
    const float* x     = (const float*)d_in[0];   // (8,1,192,192)
    const float* filt  = (const float*)d_in[1];   // (8,1,7,7)
    const float* alpha = (const float*)d_in[2];   // (8,1)
    float* out = (float*)d_out;                   // (8,8,186,186)

    dim3 block(256);
    dim3 grid((WO + TILE_X - 1) / TILE_X,   // 3
              (HO + TILE_Y - 1) / TILE_Y,   // 12
              BATCH * CO);                  // 64
    smorph_kernel<<<grid, block>>>(x, filt, alpha, out);
}

// round 7
// speedup vs baseline: 2.1456x; 1.1469x over previous
#include <cuda_runtime.h>

// SMorph: out = sum_k (x_p+f_k) e^{a(x_p+f_k)} / sum_k e^{a(x_p+f_k)}
// Factored: G=exp(a*x), H=x*G, E_k=exp(a*f_k), F_k=f_k*E_k
//   num = sum_k E_k*H + F_k*G;  den = sum_k E_k*G
// Scalar FFMA + y-register-reuse: each thread computes a 4x2 output patch;
// the 8 input rows of its footprint are loaded from smem ONCE each and
// applied to both output rows (tap row r -> out0, r-1 -> out1): -43% LDS.
// Warp = 4 row-pairs x 8 lanes -> conflict-free LDS.32 vs PITCH=71.
// Output stores: 2x STG.64 (row base only 8B-aligned since WO=186).

namespace {
constexpr int BATCH = 8;
constexpr int HH = 192, WW = 192;
constexpr int CO = 8;
constexpr int KH = 7, KW = 7;
constexpr int HO = 186, WO = 186;

constexpr int TILE_X = 64;
constexpr int TILE_Y = 32;           // 2 rows per thread
constexpr int ITX = TILE_X + KW - 1; // 70
constexpr int ITY = TILE_Y + KH - 1; // 38
constexpr int PITCH = 71;
constexpr int OPT = 4;               // outputs per thread in x
constexpr int WINW = OPT + KW - 1;   // 10
}

__global__ __launch_bounds__(256, 4)
void smorph_kernel(const float* __restrict__ x,
                   const float* __restrict__ filt,
                   const float* __restrict__ alpha,
                   float* __restrict__ out)
{
    __shared__ float sG[ITY * PITCH];
    __shared__ float sH[ITY * PITCH];
    __shared__ float2 sEF[KH * KW];   // {E, F} per tap

    const int bc  = blockIdx.z;       // b*8 + c
    const int c   = bc & 7;
    const int tid = threadIdx.x;

    const float a = alpha[c];

    if (tid < KH * KW) {
        float f = filt[c * (KH * KW) + tid];
        float e = __expf(a * f);
        sEF[tid] = make_float2(e, f * e);
    }

    const int gx0 = blockIdx.x * TILE_X;
    const int gy0 = blockIdx.y * TILE_Y;
    const float* xb = x + (bc >> 3) * (HH * WW);

    // Cooperative tile fill: G = exp(a*x), H = x*G
    for (int i = tid; i < ITY * ITX; i += 256) {
        int iy = i / ITX;
        int ix = i - iy * ITX;
        int gy = gy0 + iy;
        int gx = gx0 + ix;
        float v = (gy < HH && gx < WW) ? xb[gy * WW + gx] : 0.0f;
        float g = __expf(a * v);
        sG[iy * PITCH + ix] = g;
        sH[iy * PITCH + ix] = v * g;
    }
    __syncthreads();

    // Warp geometry: 4 row-pairs x 8 lanes; thread owns 4 cols x 2 rows.
    const int lane = tid & 31;
    const int warp = tid >> 5;        // 0..7
    const int tx = lane & 7;          // 0..7
    const int sy = lane >> 3;         // 0..3
    const int wx = warp & 1;          // 0..1
    const int wy = warp >> 1;         // 0..3
    const int lx = (wx * 8 + tx) * OPT;     // 0..60
    const int ly = (wy * 4 + sy) * 2;       // 0,2,..,30 (first output row)

    float accN[2][OPT], accD[2][OPT];
    #pragma unroll
    for (int r = 0; r < 2; r++)
        #pragma unroll
        for (int o = 0; o < OPT; o++) { accN[r][o] = 0.f; accD[r][o] = 0.f; }

    // Loop over the 8 input rows of this thread's footprint; load once,
    // feed both output rows.
    #pragma unroll
    for (int r = 0; r < KH + 1; r++) {
        const float* gr = &sG[(ly + r) * PITCH + lx];
        const float* hr = &sH[(ly + r) * PITCH + lx];
        float g[WINW], h[WINW];
        #pragma unroll
        for (int j = 0; j < WINW; j++) {
            g[j] = gr[j];
            h[j] = hr[j];
        }

        // out-row 0 uses tap row r (valid for r = 0..6)
        if (r <= KH - 1) {
            #pragma unroll
            for (int kx = 0; kx < KW; kx++) {
                const float2 ef = sEF[r * KW + kx];   // broadcast
                const float E = ef.x, F = ef.y;
                #pragma unroll
                for (int o = 0; o < OPT; o++) {
                    accN[0][o] = fmaf(E, h[kx + o], fmaf(F, g[kx + o], accN[0][o]));
                    accD[0][o] = fmaf(E, g[kx + o], accD[0][o]);
                }
            }
        }
        // out-row 1 uses tap row r-1 (valid for r = 1..7)
        if (r >= 1) {
            #pragma unroll
            for (int kx = 0; kx < KW; kx++) {
                const float2 ef = sEF[(r - 1) * KW + kx];   // broadcast
                const float E = ef.x, F = ef.y;
                #pragma unroll
                for (int o = 0; o < OPT; o++) {
                    accN[1][o] = fmaf(E, h[kx + o], fmaf(F, g[kx + o], accN[1][o]));
                    accD[1][o] = fmaf(E, g[kx + o], accD[1][o]);
                }
            }
        }
    }

    const int ox = gx0 + lx;
    #pragma unroll
    for (int r = 0; r < 2; r++) {
        const int oy = gy0 + ly + r;
        if (oy < HO) {
            float* orow = out + ((long)bc * HO + oy) * WO;
            float v0 = __fdividef(accN[r][0], accD[r][0]);
            float v1 = __fdividef(accN[r][1], accD[r][1]);
            float v2 = __fdividef(accN[r][2], accD[r][2]);
            float v3 = __fdividef(accN[r][3], accD[r][3]);
            if (ox + 3 < WO) {
                // row base is 8B-aligned (WO=186 even), never 16B for odd oy:
                // use two STG.64.
                *reinterpret_cast<float2*>(orow + ox)     = make_float2(v0, v1);
                *reinterpret_cast<float2*>(orow + ox + 2) = make_float2(v2, v3);
            } else {
                if (ox + 0 < WO) orow[ox + 0] = v0;
                if (ox + 1 < WO) orow[ox + 1] = v1;
                if (ox + 2 < WO) orow[ox + 2] = v2;
                if (ox + 3 < WO) orow[ox + 3] = v3;
            }
        }
    }
}

extern "C" void kernel_launch(void* const* d_in, const int* in_sizes, int n_in,
                              void* d_out, int out_size) {
    const float* x     = (const float*)d_in[0];   // (8,1,192,192)
    const float* filt  = (const float*)d_in[1];   // (8,1,7,7)
    const float* alpha = (const float*)d_in[2];   // (8,1)
    float* out = (float*)d_out;                   // (8,8,186,186)

    dim3 block(256);
    dim3 grid((WO + TILE_X - 1) / TILE_X,   // 3
              (HO + TILE_Y - 1) / TILE_Y,   // 6
              BATCH * CO);                  // 64
    smorph_kernel<<<grid, block>>>(x, filt, alpha, out);
}